// round 2
// baseline (speedup 1.0000x reference)
#include <cuda_runtime.h>
#include <math_constants.h>

// Problem: B=32, T=2048, D=512, fp32
//   energy[b,t]    = dot(key[b,t,:], query[b,:])
//   attention[b,t] = softmax_T(energy)[b,t]
//   out[b,d]       = sum_t attention[b,t] * value[b,t,d]
// d_out layout: out (32*512 = 16384 floats) followed by attention (32*2048 = 65536 floats)

#define B 32
#define T 2048
#define D 512
#define TSPLIT 8
#define TCHUNK (T / TSPLIT)  // 256

// Scratch (no allocations allowed in kernel_launch)
__device__ float g_energy[B * T];
__device__ float g_partial[B * TSPLIT * D];

// ---------------------------------------------------------------------------
// Kernel 1: energy[b,t] = key[b,t,:] . query[b,:]
// One warp per (b,t) row. Each lane: 4x float4 loads, FMA, warp reduce.
// ---------------------------------------------------------------------------
__global__ void energy_kernel(const float* __restrict__ query,
                              const float* __restrict__ key,
                              float* __restrict__ energy) {
    int warp = (blockIdx.x * blockDim.x + threadIdx.x) >> 5;  // 0..B*T-1
    int lane = threadIdx.x & 31;
    int b = warp >> 11;  // T = 2048 = 2^11

    const float4* krow = (const float4*)(key + (size_t)warp * D);
    const float4* qrow = (const float4*)(query + (size_t)b * D);

    float acc = 0.0f;
#pragma unroll
    for (int i = 0; i < 4; i++) {
        float4 kv = krow[lane + 32 * i];
        float4 qv = qrow[lane + 32 * i];  // hot in L1/L2 (q is 64 KB total)
        acc += kv.x * qv.x + kv.y * qv.y + kv.z * qv.z + kv.w * qv.w;
    }
#pragma unroll
    for (int off = 16; off; off >>= 1)
        acc += __shfl_xor_sync(0xFFFFFFFFu, acc, off);

    if (lane == 0) energy[warp] = acc;
}

// ---------------------------------------------------------------------------
// Kernel 2: softmax over T per batch. 32 blocks x 256 threads, 8 vals/thread.
// Writes attention directly into its d_out slice.
// ---------------------------------------------------------------------------
__global__ void softmax_kernel(const float* __restrict__ energy,
                               float* __restrict__ attn) {
    int b = blockIdx.x;
    int tid = threadIdx.x;  // 0..255
    __shared__ float red[256];

    const float* e = energy + (size_t)b * T;
    float vals[8];
    float m = -CUDART_INF_F;
#pragma unroll
    for (int i = 0; i < 8; i++) {
        vals[i] = e[tid + 256 * i];
        m = fmaxf(m, vals[i]);
    }

    red[tid] = m;
    __syncthreads();
#pragma unroll
    for (int s = 128; s; s >>= 1) {
        if (tid < s) red[tid] = fmaxf(red[tid], red[tid + s]);
        __syncthreads();
    }
    m = red[0];
    __syncthreads();

    float sum = 0.0f;
#pragma unroll
    for (int i = 0; i < 8; i++) {
        vals[i] = __expf(vals[i] - m);
        sum += vals[i];
    }

    red[tid] = sum;
    __syncthreads();
#pragma unroll
    for (int s = 128; s; s >>= 1) {
        if (tid < s) red[tid] += red[tid + s];
        __syncthreads();
    }
    float inv = 1.0f / red[0];

    float* arow = attn + (size_t)b * T;
#pragma unroll
    for (int i = 0; i < 8; i++)
        arow[tid + 256 * i] = vals[i] * inv;
}

// ---------------------------------------------------------------------------
// Kernel 3: partial[b,ts,:] = sum_{t in chunk ts} attn[b,t] * value[b,t,:]
// Grid (TSPLIT, B), 128 threads; each thread owns one float4 of D.
// ---------------------------------------------------------------------------
__global__ void av_kernel(const float* __restrict__ attn,
                          const float* __restrict__ value,
                          float* __restrict__ partial) {
    int ts = blockIdx.x;
    int b = blockIdx.y;
    int tid = threadIdx.x;  // 0..127

    __shared__ float sa[TCHUNK];
    int t0 = ts * TCHUNK;
    sa[tid]       = attn[(size_t)b * T + t0 + tid];
    sa[tid + 128] = attn[(size_t)b * T + t0 + tid + 128];
    __syncthreads();

    const float4* v = (const float4*)(value + ((size_t)b * T + t0) * D);
    float4 acc = make_float4(0.f, 0.f, 0.f, 0.f);

#pragma unroll 4
    for (int t = 0; t < TCHUNK; t++) {
        float a = sa[t];
        float4 vv = v[(size_t)t * (D / 4) + tid];
        acc.x += a * vv.x;
        acc.y += a * vv.y;
        acc.z += a * vv.z;
        acc.w += a * vv.w;
    }

    ((float4*)partial)[((size_t)b * TSPLIT + ts) * (D / 4) + tid] = acc;
}

// ---------------------------------------------------------------------------
// Kernel 4: out[b,d] = sum_ts partial[b,ts,d]
// ---------------------------------------------------------------------------
__global__ void reduce_kernel(const float* __restrict__ partial,
                              float* __restrict__ out) {
    int i = blockIdx.x * blockDim.x + threadIdx.x;  // 0..B*D-1
    int b = i >> 9;   // D = 512
    int d = i & 511;
    float s = 0.0f;
#pragma unroll
    for (int ts = 0; ts < TSPLIT; ts++)
        s += partial[((size_t)b * TSPLIT + ts) * D + d];
    out[i] = s;
}

extern "C" void kernel_launch(void* const* d_in, const int* in_sizes, int n_in,
                              void* d_out, int out_size) {
    const float* query = (const float*)d_in[0];  // [B, D]
    const float* key   = (const float*)d_in[1];  // [B, T, D]
    const float* value = (const float*)d_in[2];  // [B, T, D]

    float* out  = (float*)d_out;            // [B, D]
    float* attn = (float*)d_out + B * D;    // [B, T]

    float* energy;
    float* partial;
    cudaGetSymbolAddress((void**)&energy, g_energy);
    cudaGetSymbolAddress((void**)&partial, g_partial);

    // 1) energy: one warp per row, 8 warps/block
    {
        int warps = B * T;               // 65536
        int blocks = warps / 8;          // 8192
        energy_kernel<<<blocks, 256>>>(query, key, energy);
    }
    // 2) softmax -> attention slice of d_out
    softmax_kernel<<<B, 256>>>(energy, attn);
    // 3) attn @ value partials
    {
        dim3 grid(TSPLIT, B);
        av_kernel<<<grid, 128>>>(attn, value, partial);
    }
    // 4) reduce partials -> out slice of d_out
    reduce_kernel<<<(B * D) / 256, 256>>>(partial, out);
}

// round 4
// speedup vs baseline: 1.3248x; 1.3248x over previous
#include <cuda_runtime.h>
#include <math_constants.h>

// Problem: B=32, T=2048, D=512, fp32
//   energy[b,t]    = dot(key[b,t,:], query[b,:])
//   attention[b,t] = softmax_T(energy)[b,t]
//   out[b,d]       = sum_t attention[b,t] * value[b,t,d]
// d_out layout: out (32*512 = 16384 floats) then attention (32*2048 = 65536 floats)

#define B 32
#define T 2048
#define D 512
#define TSPLIT 32
#define TCHUNK (T / TSPLIT)  // 64

// Scratch (no allocations allowed in kernel_launch)
__device__ float g_energy[B * T];
__device__ float g_partial[B * TSPLIT * D];

// ---------------------------------------------------------------------------
// Kernel 1: energy[b,t] = key[b,t,:] . query[b,:]
// One warp per (b,t) row. Each lane: 4x float4 loads, FMA, warp reduce.
// ---------------------------------------------------------------------------
__global__ void energy_kernel(const float* __restrict__ query,
                              const float* __restrict__ key,
                              float* __restrict__ energy) {
    int warp = (blockIdx.x * blockDim.x + threadIdx.x) >> 5;  // 0..B*T-1
    int lane = threadIdx.x & 31;
    int b = warp >> 11;  // T = 2048 = 2^11

    const float4* krow = (const float4*)(key + (size_t)warp * D);
    const float4* qrow = (const float4*)(query + (size_t)b * D);

    // Front-batch the K loads (streaming, DRAM) for max MLP; q hits L1/L2.
    float4 kv[4], qv[4];
#pragma unroll
    for (int i = 0; i < 4; i++) kv[i] = krow[lane + 32 * i];
#pragma unroll
    for (int i = 0; i < 4; i++) qv[i] = qrow[lane + 32 * i];

    float acc = 0.0f;
#pragma unroll
    for (int i = 0; i < 4; i++)
        acc += kv[i].x * qv[i].x + kv[i].y * qv[i].y +
               kv[i].z * qv[i].z + kv[i].w * qv[i].w;

#pragma unroll
    for (int off = 16; off; off >>= 1)
        acc += __shfl_xor_sync(0xFFFFFFFFu, acc, off);

    if (lane == 0) energy[warp] = acc;
}

// ---------------------------------------------------------------------------
// Kernel 2: softmax over T per batch. 32 blocks x 256 threads, 8 vals/thread.
// ---------------------------------------------------------------------------
__global__ void softmax_kernel(const float* __restrict__ energy,
                               float* __restrict__ attn) {
    int b = blockIdx.x;
    int tid = threadIdx.x;  // 0..255
    __shared__ float red[256];

    const float* e = energy + (size_t)b * T;
    float vals[8];
    float m = -CUDART_INF_F;
#pragma unroll
    for (int i = 0; i < 8; i++) {
        vals[i] = e[tid + 256 * i];
        m = fmaxf(m, vals[i]);
    }

    red[tid] = m;
    __syncthreads();
#pragma unroll
    for (int s = 128; s; s >>= 1) {
        if (tid < s) red[tid] = fmaxf(red[tid], red[tid + s]);
        __syncthreads();
    }
    m = red[0];
    __syncthreads();

    float sum = 0.0f;
#pragma unroll
    for (int i = 0; i < 8; i++) {
        vals[i] = __expf(vals[i] - m);
        sum += vals[i];
    }

    red[tid] = sum;
    __syncthreads();
#pragma unroll
    for (int s = 128; s; s >>= 1) {
        if (tid < s) red[tid] += red[tid + s];
        __syncthreads();
    }
    float inv = 1.0f / red[0];

    float* arow = attn + (size_t)b * T;
#pragma unroll
    for (int i = 0; i < 8; i++)
        arow[tid + 256 * i] = vals[i] * inv;
}

// ---------------------------------------------------------------------------
// Kernel 3: partial[b,ts,:] = sum_{t in chunk ts} attn[b,t] * value[b,t,:]
// Grid (TSPLIT, B) = 1024 blocks, 128 threads; thread owns one float4 of D.
// TCHUNK=64 t-rows per block, unroll 8 -> deep MLP, ~28 warps/SM.
// ---------------------------------------------------------------------------
__global__ void av_kernel(const float* __restrict__ attn,
                          const float* __restrict__ value,
                          float* __restrict__ partial) {
    int ts = blockIdx.x;
    int b = blockIdx.y;
    int tid = threadIdx.x;  // 0..127

    __shared__ float sa[TCHUNK];
    int t0 = ts * TCHUNK;
    if (tid < TCHUNK) sa[tid] = attn[(size_t)b * T + t0 + tid];
    __syncthreads();

    const float4* v = (const float4*)(value + ((size_t)b * T + t0) * D);
    float4 acc = make_float4(0.f, 0.f, 0.f, 0.f);

#pragma unroll 8
    for (int t = 0; t < TCHUNK; t++) {
        float a = sa[t];
        float4 vv = v[(size_t)t * (D / 4) + tid];
        acc.x += a * vv.x;
        acc.y += a * vv.y;
        acc.z += a * vv.z;
        acc.w += a * vv.w;
    }

    ((float4*)partial)[((size_t)b * TSPLIT + ts) * (D / 4) + tid] = acc;
}

// ---------------------------------------------------------------------------
// Kernel 4: out[b,d] = sum_ts partial[b,ts,d]  (float4-vectorized)
// ---------------------------------------------------------------------------
__global__ void reduce_kernel(const float* __restrict__ partial,
                              float* __restrict__ out) {
    int i = blockIdx.x * blockDim.x + threadIdx.x;  // 0..B*D/4-1
    int b = i >> 7;    // D/4 = 128
    int d4 = i & 127;

    const float4* p = (const float4*)partial;
    float4 s = make_float4(0.f, 0.f, 0.f, 0.f);
#pragma unroll
    for (int ts = 0; ts < TSPLIT; ts++) {
        float4 v = p[((size_t)b * TSPLIT + ts) * (D / 4) + d4];
        s.x += v.x; s.y += v.y; s.z += v.z; s.w += v.w;
    }
    ((float4*)out)[i] = s;
}

extern "C" void kernel_launch(void* const* d_in, const int* in_sizes, int n_in,
                              void* d_out, int out_size) {
    const float* query = (const float*)d_in[0];  // [B, D]
    const float* key   = (const float*)d_in[1];  // [B, T, D]
    const float* value = (const float*)d_in[2];  // [B, T, D]

    float* out  = (float*)d_out;            // [B, D]
    float* attn = (float*)d_out + B * D;    // [B, T]

    float* energy;
    float* partial;
    cudaGetSymbolAddress((void**)&energy, g_energy);
    cudaGetSymbolAddress((void**)&partial, g_partial);

    // 1) energy: one warp per row, 8 warps/block
    energy_kernel<<<(B * T) / 8, 256>>>(query, key, energy);
    // 2) softmax -> attention slice of d_out
    softmax_kernel<<<B, 256>>>(energy, attn);
    // 3) attn @ value partials
    {
        dim3 grid(TSPLIT, B);
        av_kernel<<<grid, 128>>>(attn, value, partial);
    }
    // 4) reduce partials -> out slice of d_out
    reduce_kernel<<<(B * D / 4) / 256, 256>>>(partial, out);
}

// round 5
// speedup vs baseline: 1.4006x; 1.0572x over previous
#include <cuda_runtime.h>
#include <math_constants.h>

// Problem: B=32, T=2048, D=512, fp32
//   energy[b,t]    = dot(key[b,t,:], query[b,:])
//   attention[b,t] = softmax_T(energy)[b,t]
//   out[b,d]       = sum_t attention[b,t] * value[b,t,d]
// d_out layout: out (32*512 = 16384 floats) then attention (32*2048 = 65536 floats)

#define B 32
#define T 2048
#define D 512
#define TSPLIT 32
#define TCHUNK (T / TSPLIT)  // 64

// Scratch (no allocations allowed in kernel_launch)
__device__ float g_energy[B * T];

// ---------------------------------------------------------------------------
// Kernel 1: energy[b,t] = key[b,t,:] . query[b,:]
// One warp per (b,t) row. Front-batched loads for MLP, warp shuffle reduce.
// ---------------------------------------------------------------------------
__global__ void energy_kernel(const float* __restrict__ query,
                              const float* __restrict__ key,
                              float* __restrict__ energy) {
    int warp = (blockIdx.x * blockDim.x + threadIdx.x) >> 5;  // 0..B*T-1
    int lane = threadIdx.x & 31;
    int b = warp >> 11;  // T = 2048 = 2^11

    const float4* krow = (const float4*)(key + (size_t)warp * D);
    const float4* qrow = (const float4*)(query + (size_t)b * D);

    float4 kv[4], qv[4];
#pragma unroll
    for (int i = 0; i < 4; i++) kv[i] = krow[lane + 32 * i];
#pragma unroll
    for (int i = 0; i < 4; i++) qv[i] = qrow[lane + 32 * i];

    float acc = 0.0f;
#pragma unroll
    for (int i = 0; i < 4; i++)
        acc += kv[i].x * qv[i].x + kv[i].y * qv[i].y +
               kv[i].z * qv[i].z + kv[i].w * qv[i].w;

#pragma unroll
    for (int off = 16; off; off >>= 1)
        acc += __shfl_xor_sync(0xFFFFFFFFu, acc, off);

    if (lane == 0) energy[warp] = acc;
}

// ---------------------------------------------------------------------------
// Kernel 2: softmax over T per batch. 32 blocks x 256 threads, 8 vals/thread.
// ---------------------------------------------------------------------------
__global__ void softmax_kernel(const float* __restrict__ energy,
                               float* __restrict__ attn) {
    int b = blockIdx.x;
    int tid = threadIdx.x;  // 0..255
    __shared__ float red[256];

    const float* e = energy + (size_t)b * T;
    float vals[8];
    float m = -CUDART_INF_F;
#pragma unroll
    for (int i = 0; i < 8; i++) {
        vals[i] = e[tid + 256 * i];
        m = fmaxf(m, vals[i]);
    }

    red[tid] = m;
    __syncthreads();
#pragma unroll
    for (int s = 128; s; s >>= 1) {
        if (tid < s) red[tid] = fmaxf(red[tid], red[tid + s]);
        __syncthreads();
    }
    m = red[0];
    __syncthreads();

    float sum = 0.0f;
#pragma unroll
    for (int i = 0; i < 8; i++) {
        vals[i] = __expf(vals[i] - m);
        sum += vals[i];
    }

    red[tid] = sum;
    __syncthreads();
#pragma unroll
    for (int s = 128; s; s >>= 1) {
        if (tid < s) red[tid] += red[tid + s];
        __syncthreads();
    }
    float inv = 1.0f / red[0];

    float* arow = attn + (size_t)b * T;
#pragma unroll
    for (int i = 0; i < 8; i++)
        arow[tid + 256 * i] = vals[i] * inv;
}

// ---------------------------------------------------------------------------
// Kernel 3: out[b,:] += sum_{t in chunk ts} attn[b,t] * value[b,t,:]
// Grid (TSPLIT, B) = 1024 blocks, 128 threads; thread owns one float4 of D.
// Accumulates directly into out via REDG (no partial round-trip, no reduce).
// ---------------------------------------------------------------------------
__global__ void av_kernel(const float* __restrict__ attn,
                          const float* __restrict__ value,
                          float* __restrict__ out) {
    int ts = blockIdx.x;
    int b = blockIdx.y;
    int tid = threadIdx.x;  // 0..127

    __shared__ float sa[TCHUNK];
    int t0 = ts * TCHUNK;
    if (tid < TCHUNK) sa[tid] = attn[(size_t)b * T + t0 + tid];
    __syncthreads();

    const float4* v = (const float4*)(value + ((size_t)b * T + t0) * D);
    float4 acc = make_float4(0.f, 0.f, 0.f, 0.f);

#pragma unroll 8
    for (int t = 0; t < TCHUNK; t++) {
        float a = sa[t];
        float4 vv = v[(size_t)t * (D / 4) + tid];
        acc.x += a * vv.x;
        acc.y += a * vv.y;
        acc.z += a * vv.z;
        acc.w += a * vv.w;
    }

    float* o = out + (size_t)b * D + tid * 4;
    atomicAdd(o + 0, acc.x);
    atomicAdd(o + 1, acc.y);
    atomicAdd(o + 2, acc.z);
    atomicAdd(o + 3, acc.w);
}

extern "C" void kernel_launch(void* const* d_in, const int* in_sizes, int n_in,
                              void* d_out, int out_size) {
    const float* query = (const float*)d_in[0];  // [B, D]
    const float* key   = (const float*)d_in[1];  // [B, T, D]
    const float* value = (const float*)d_in[2];  // [B, T, D]

    float* out  = (float*)d_out;            // [B, D]
    float* attn = (float*)d_out + B * D;    // [B, T]

    float* energy;
    cudaGetSymbolAddress((void**)&energy, g_energy);

    // Zero the out slice (memset node — graph-capturable, no allocation).
    cudaMemsetAsync(out, 0, (size_t)B * D * sizeof(float), 0);

    // 1) energy: one warp per row, 8 warps/block
    energy_kernel<<<(B * T) / 8, 256>>>(query, key, energy);
    // 2) softmax -> attention slice of d_out
    softmax_kernel<<<B, 256>>>(energy, attn);
    // 3) attn @ value, accumulated straight into out
    {
        dim3 grid(TSPLIT, B);
        av_kernel<<<grid, 128>>>(attn, value, out);
    }
}